// round 2
// baseline (speedup 1.0000x reference)
#include <cuda_runtime.h>

// ---------------------------------------------------------------------------
// WeatherForecastingModel: 2-layer LSTM encoder (168 steps) + O(T^2)
// autoregressive decoder replay (sum_{k=1}^{168} k = 14196 steps).
// Total 14364 strictly sequential LSTM cell steps; batch elements (B=8) are
// independent chains.
//
// Layout: 8 groups (one per batch element) x 8 CTAs. Each CTA owns 16 hidden
// units (64 gate rows: i,f,g,o x 16) of BOTH layers; weights live in SMEM.
// Group-internal synchronization: monotonic global atomic barrier.
// h-state: double-buffered in global (ping-pong per step) -> no WAR races.
// c-state: private to the owning CTA (SMEM).
// ---------------------------------------------------------------------------

#define H     128
#define CPG   8               // CTAs per group
#define NG    8               // groups == batch
#define NCTA  (NG*CPG)        // 64
#define NTH   256
#define TENC  168
#define FLEN  168

// SMEM layout (floats). Gate rows are stored as 4 chunks of 64, each padded
// to 65 so that lanes (rr,p) hit distinct banks: bank = (4*rr + p + j) % 32.
#define OFF_W  0
#define SZ_W   (2*64*4*65)        // 33280: [layer][row rr][chunk p][65]
#define OFF_B  (OFF_W + SZ_W)     // 33280
#define SZ_B   128                // combined bias b_ih + b_hh, [layer][64]
#define OFF_IN (OFF_B + SZ_B)     // 33408
#define SZ_IN  (4*65)             // input vector [x(128)|h(128)] in 4 chunks
#define OFF_G  (OFF_IN + SZ_IN)   // 33668
#define SZ_G   64                 // reduced gate values
#define OFF_C  (OFF_G + SZ_G)     // 33732
#define SZ_C   32                 // c-state [layer][16]
#define SMEM_FLOATS (OFF_C + SZ_C)        // 33764
#define SMEM_BYTES  (SMEM_FLOATS * 4)     // 135056

// Global scratch (allocation-free per harness rules)
__device__ float    gH[NG][2][2][H];       // [group][layer][ping-pong][H]
__device__ float    gBuf[NG][FLEN + 1][H]; // decoder replay buffer
__device__ unsigned gBar[NG];              // per-group monotonic barrier ctr

__device__ __forceinline__ float sigf(float v) { return 1.0f / (1.0f + expf(-v)); }

// Monotonic-counter group barrier (all CTAs of a group co-resident).
__device__ __forceinline__ void group_barrier(int grp, unsigned &target)
{
    target += CPG;
    __syncthreads();
    if (threadIdx.x == 0) {
        __threadfence();                 // publish this CTA's global writes
        atomicAdd(&gBar[grp], 1u);
        volatile unsigned *vp = &gBar[grp];
        while (*vp < target) { }
        __threadfence();
    }
    __syncthreads();
}

// Compute 64 gate rows (4 gates x 16 units) for layer l from sm[OFF_IN],
// then combine gates -> (c,h). Writes new h (16 units) to hout[] (global),
// optionally records it to rec[] as well.
__device__ __forceinline__ void dot_combine(float *sm, int l, int cl,
                                            float *hout, float *rec)
{
    const int tid = threadIdx.x;
    const int rr  = tid >> 2;        // gate row within CTA: gate*16 + unit
    const int p   = tid & 3;         // split-K quarter (64 terms each)

    const float *wrow = &sm[OFF_W + ((l * 64 + rr) * 4 + p) * 65];
    const float *iv   = &sm[OFF_IN + p * 65];

    float a0 = 0.f, a1 = 0.f, a2 = 0.f, a3 = 0.f;
#pragma unroll
    for (int j = 0; j < 64; j += 4) {
        a0 += wrow[j    ] * iv[j    ];
        a1 += wrow[j + 1] * iv[j + 1];
        a2 += wrow[j + 2] * iv[j + 2];
        a3 += wrow[j + 3] * iv[j + 3];
    }
    float acc = (a0 + a1) + (a2 + a3);
    // reduce the 4 split-K partials (lanes form quads: masks 1,2 stay in-quad)
    acc += __shfl_xor_sync(0xffffffffu, acc, 1);
    acc += __shfl_xor_sync(0xffffffffu, acc, 2);
    if (p == 0) sm[OFF_G + rr] = acc + sm[OFF_B + l * 64 + rr];
    __syncthreads();

    if (tid < 16) {                          // one thread per owned unit
        float gi = sm[OFF_G + tid];
        float gf = sm[OFF_G + 16 + tid];
        float gg = sm[OFF_G + 32 + tid];
        float go = sm[OFF_G + 48 + tid];
        float cold = sm[OFF_C + l * 16 + tid];
        float cn = sigf(gf) * cold + sigf(gi) * tanhf(gg);
        float hn = sigf(go) * tanhf(cn);
        sm[OFF_C + l * 16 + tid] = cn;
        int unit = cl * 16 + tid;
        hout[unit] = hn;
        if (rec) rec[unit] = hn;
    }
}

// One full 2-layer LSTM cell step. s = global step counter (selects ping-pong).
__device__ __forceinline__ void lstm_step(float *sm, int grp, int cl, int s,
                                          const float *xsrc, float *rec,
                                          unsigned &bt)
{
    const int tid = threadIdx.x;
    const int rp = s & 1, wp = rp ^ 1;

    // ---- layer 1: gates = x @ Wih1^T + h1 @ Whh1^T + b ----
    {
        int p = tid >> 6, j = tid & 63;
        float v = (p < 2) ? __ldcg(&xsrc[p * 64 + j])
                          : __ldcg(&gH[grp][0][rp][(p - 2) * 64 + j]);
        sm[OFF_IN + p * 65 + j] = v;
    }
    __syncthreads();
    dot_combine(sm, 0, cl, &gH[grp][0][wp][0], (float *)0);
    group_barrier(grp, bt);

    // ---- layer 2: x = new h1, h = h2 ----
    {
        int p = tid >> 6, j = tid & 63;
        float v = (p < 2) ? __ldcg(&gH[grp][0][wp][p * 64 + j])
                          : __ldcg(&gH[grp][1][rp][(p - 2) * 64 + j]);
        sm[OFF_IN + p * 65 + j] = v;
    }
    __syncthreads();
    dot_combine(sm, 1, cl, &gH[grp][1][wp][0], rec);
    group_barrier(grp, bt);
}

__global__ void __launch_bounds__(NTH, 1) wfm_kernel(
    const float *__restrict__ X,   const float *__restrict__ Wih,
    const float *__restrict__ Whh, const float *__restrict__ bih,
    const float *__restrict__ bhh, const float *__restrict__ Wfc,
    const float *__restrict__ bfc, float *__restrict__ OUT)
{
    extern __shared__ float sm[];
    const int tid = threadIdx.x;
    const int grp = blockIdx.x >> 3;   // batch element
    const int cl  = blockIdx.x & 7;    // CTA within group (owns units cl*16..+16)

    // ---- stage weights into SMEM (concatenated [Wih_row | Whh_row]) ----
    for (int e = tid; e < 2 * 64 * 256; e += NTH) {
        int l   = e >> 14;
        int rem = e & 16383;
        int rr  = rem >> 8;
        int c   = rem & 255;
        int p   = c >> 6;
        int j   = c & 63;
        int gate = rr >> 4, u = rr & 15;
        int r = gate * H + cl * 16 + u;       // PyTorch gate-row order i,f,g,o
        float v = (p < 2) ? __ldg(&Wih[(l * 512 + r) * H + p * 64 + j])
                          : __ldg(&Whh[(l * 512 + r) * H + (p - 2) * 64 + j]);
        sm[OFF_W + ((l * 64 + rr) * 4 + p) * 65 + j] = v;
    }
    for (int e = tid; e < 128; e += NTH) {
        int l = e >> 6, rr = e & 63;
        int gate = rr >> 4, u = rr & 15;
        int r = gate * H + cl * 16 + u;
        sm[OFF_B + e] = __ldg(&bih[l * 512 + r]) + __ldg(&bhh[l * 512 + r]);
    }
    // ---- zero this launch's state (graph replays reuse the globals) ----
    if (tid < 16) {
        int unit = cl * 16 + tid;
#pragma unroll
        for (int l = 0; l < 2; l++) {
            gH[grp][l][0][unit] = 0.f;
            gH[grp][l][1][unit] = 0.f;
            sm[OFF_C + l * 16 + tid] = 0.f;
        }
    }
    unsigned bt = 0;
    group_barrier(grp, bt);

    int s = 0;

    // ---------------- encoder ----------------
    for (int t = 0; t < TENC; t++) {
        const float *xs = &X[(grp * TENC + t) * H];
        float *rec = (t == TENC - 1) ? &gBuf[grp][0][0] : (float *)0;
        lstm_step(sm, grp, cl, s, xs, rec, bt);
        s++;
    }

    // ---------------- decoder: O(T^2) replay ----------------
    for (int k = 0; k < FLEN; k++) {
        for (int t = 0; t <= k; t++) {
            float *bp = &gBuf[grp][t][0];     // input == record target (WAR
            lstm_step(sm, grp, cl, s, bp, bp, bt); // protected by mid barrier)
            s++;
        }
        // forecast = out[k] @ Wfc^T + bfc ; feeds buf[k+1] and OUT[:,k,:]
        if (cl == 0) {
            int hp = s & 1;                    // parity last step wrote
            if (tid < H) sm[OFF_IN + tid] = __ldcg(&gH[grp][1][hp][tid]);
            __syncthreads();
            if (tid < H) {
                float acc = __ldg(&bfc[tid]);
                const float *wr = &Wfc[tid * H];
#pragma unroll 16
                for (int m = 0; m < H; m++) acc += sm[OFF_IN + m] * __ldg(&wr[m]);
                OUT[(grp * FLEN + k) * H + tid] = acc;
                gBuf[grp][k + 1][tid] = acc;
            }
        }
        group_barrier(grp, bt);
    }
}

__global__ void init_kernel()
{
    if (threadIdx.x < NG) gBar[threadIdx.x] = 0u;
}

extern "C" void kernel_launch(void *const *d_in, const int *in_sizes, int n_in,
                              void *d_out, int out_size)
{
    const float *X   = (const float *)d_in[0];
    const float *Wih = (const float *)d_in[1];
    const float *Whh = (const float *)d_in[2];
    const float *bih = (const float *)d_in[3];
    const float *bhh = (const float *)d_in[4];
    const float *Wfc = (const float *)d_in[5];
    const float *bfc = (const float *)d_in[6];
    float *OUT = (float *)d_out;

    cudaFuncSetAttribute(wfm_kernel,
                         cudaFuncAttributeMaxDynamicSharedMemorySize,
                         SMEM_BYTES);
    init_kernel<<<1, 32>>>();
    wfm_kernel<<<NCTA, NTH, SMEM_BYTES>>>(X, Wih, Whh, bih, bhh, Wfc, bfc, OUT);
}

// round 3
// speedup vs baseline: 1.8362x; 1.8362x over previous
#include <cuda_runtime.h>
#include <cstdint>

// ---------------------------------------------------------------------------
// 2-layer LSTM encoder (168 steps) + O(T^2) decoder replay (14196 steps).
// 8 clusters (one per batch element) x 8 CTAs. Weights in REGISTERS
// (64 gate-row weights x 2 layers per thread). Replay buffer, X, Wfc in SMEM
// (full replica per CTA). Cross-CTA h exchange via DSMEM st.shared::cluster
// + mbarrier arrive/wait. Deferred waits: one exposed exchange per step.
// ---------------------------------------------------------------------------

#define H     128
#define CPG   8
#define NTH   256
#define TENC  168
#define FLEN  168

// SMEM float offsets
#define OFF_BUF 0                        // replay buffer / X: 169*128
#define OFF_WFC (169*128)                // Wfc, stride 129:   128*129
#define OFF_BFC (OFF_WFC + 128*129)      // bfc:               128
#define OFF_HB  (OFF_BFC + 128)          // h[(l*2+par)*128]:  512
#define OFF_GT  (OFF_HB + 512)           // reduced gates:     64
#define OFF_HS  (OFF_GT + 64)            // h stage:           16
#define OFF_MB  (OFF_HS + 16)            // mbA (8B) + mbB (8B)
#define SMEM_FLOATS (OFF_MB + 4)
#define SMEM_BYTES  (SMEM_FLOATS * 4)    // 155472 B

static __device__ __forceinline__ float sigf(float v) { return 1.0f / (1.0f + expf(-v)); }

static __device__ __forceinline__ uint32_t s2u(const void *p)
{
    uint32_t a;
    asm("{ .reg .u64 t; cvta.to.shared.u64 t, %1; cvt.u32.u64 %0, t; }"
        : "=r"(a) : "l"(p));
    return a;
}
static __device__ __forceinline__ uint32_t mapa32(uint32_t a, uint32_t r)
{
    uint32_t d;
    asm("mapa.shared::cluster.u32 %0, %1, %2;" : "=r"(d) : "r"(a), "r"(r));
    return d;
}
static __device__ __forceinline__ void stc4(uint32_t a, float4 v)
{
    asm volatile("st.shared::cluster.v4.f32 [%0], {%1,%2,%3,%4};"
                 :: "r"(a), "f"(v.x), "f"(v.y), "f"(v.z), "f"(v.w) : "memory");
}
static __device__ __forceinline__ void arrive_rel(uint32_t a)
{
    asm volatile("mbarrier.arrive.release.cluster.shared::cluster.b64 _, [%0];"
                 :: "r"(a) : "memory");
}
static __device__ __forceinline__ void waitp(uint32_t a, uint32_t ph)
{
    asm volatile("{ .reg .pred P;\n"
                 "WL%=:\n"
                 " mbarrier.try_wait.parity.acquire.cluster.shared::cta.b64 P, [%0], %1;\n"
                 " @!P bra WL%=;\n"
                 "}" :: "r"(a), "r"(ph) : "memory");
}
static __device__ __forceinline__ void mbinit(uint32_t a, uint32_t n)
{
    asm volatile("mbarrier.init.shared.b64 [%0], %1;" :: "r"(a), "r"(n) : "memory");
}

// 64-term dot: weights in registers (constant indices), input via LDS.128.
static __device__ __forceinline__ float dot64(const float *__restrict__ w,
                                              const float *__restrict__ s)
{
    const float4 *v = (const float4 *)s;
    float a0 = 0.f, a1 = 0.f, a2 = 0.f, a3 = 0.f;
#pragma unroll
    for (int q = 0; q < 16; q++) {
        float4 t = v[q];
        a0 = fmaf(w[4 * q + 0], t.x, a0);
        a1 = fmaf(w[4 * q + 1], t.y, a1);
        a2 = fmaf(w[4 * q + 2], t.z, a2);
        a3 = fmaf(w[4 * q + 3], t.w, a3);
    }
    return (a0 + a1) + (a2 + a3);
}

__global__ void __launch_bounds__(NTH, 1) wfm_kernel(
    const float *__restrict__ X,   const float *__restrict__ Wih,
    const float *__restrict__ Whh, const float *__restrict__ bih,
    const float *__restrict__ bhh, const float *__restrict__ Wfc,
    const float *__restrict__ bfc, float *__restrict__ OUT)
{
    extern __shared__ float sm[];
    const int tid  = threadIdx.x;
    const int grp  = blockIdx.x >> 3;   // batch element (cluster id)
    const int cl   = blockIdx.x & 7;    // cluster rank; owns units cl*16..+15
    const int rr   = tid >> 2;          // gate row: gate*16 + unit
    const int p    = tid & 3;           // split-K quarter (64 cols)
    const int gate = rr >> 4, u = rr & 15;

    // ---- weights -> registers (64 per layer per thread) ----
    float w0[64], w1[64];
    {
        const int row = gate * H + cl * 16 + u;
        const float *s0 = (p < 2) ? &Wih[row * H + p * 64]
                                  : &Whh[row * H + (p - 2) * 64];
        const float *s1 = (p < 2) ? &Wih[(512 + row) * H + p * 64]
                                  : &Whh[(512 + row) * H + (p - 2) * 64];
#pragma unroll
        for (int j = 0; j < 64; j++) { w0[j] = __ldg(s0 + j); w1[j] = __ldg(s1 + j); }
    }
    const int brow = gate * H + cl * 16 + u;
    const float bia0 = __ldg(&bih[brow]) + __ldg(&bhh[brow]);
    const float bia1 = __ldg(&bih[512 + brow]) + __ldg(&bhh[512 + brow]);

    // ---- SMEM staging: X into replay buffer, Wfc (pad 129), bfc, zero HB ----
    for (int i = tid; i < TENC * H; i += NTH)
        sm[OFF_BUF + i] = __ldg(&X[grp * TENC * H + i]);
    for (int i = tid; i < H * H; i += NTH) {
        int r = i >> 7, c = i & 127;
        sm[OFF_WFC + r * 129 + c] = __ldg(&Wfc[i]);
    }
    if (tid < H) sm[OFF_BFC + tid] = __ldg(&bfc[tid]);
    for (int i = tid; i < 512; i += NTH) sm[OFF_HB + i] = 0.f;

    const uint32_t mbA = s2u(&sm[OFF_MB]);
    const uint32_t mbB = mbA + 8;
    if (tid == 0) { mbinit(mbA, CPG); mbinit(mbB, CPG); }
    __syncthreads();
    asm volatile("barrier.cluster.arrive.aligned;" ::: "memory");
    asm volatile("barrier.cluster.wait.aligned;"   ::: "memory");

    // ---- pusher (tid<8, one per destination rank) remote addresses ----
    uint32_t mbA_r = 0, mbB_r = 0, bufr = 0;
    uint32_t h1d0 = 0, h1d1 = 0, h2d0 = 0, h2d1 = 0;
    if (tid < 8) {
        uint32_t base = s2u(sm);
        mbA_r = mapa32(base + OFF_MB * 4, tid);
        mbB_r = mbA_r + 8;
        bufr  = mapa32(base + OFF_BUF * 4, tid);
        uint32_t hb = base + OFF_HB * 4 + cl * 16 * 4;
        h1d0 = mapa32(hb + 0 * 512, tid);     // HB[l=0][par=0]
        h1d1 = mapa32(hb + 1 * 512, tid);     // HB[l=0][par=1]
        h2d0 = mapa32(hb + 2 * 512, tid);     // HB[l=1][par=0]
        h2d1 = mapa32(hb + 3 * 512, tid);     // HB[l=1][par=1]
    }

    float c0 = 0.f, c1 = 0.f;                 // c-state (tid<16 threads)
    int s = 0, adone = 0, bdone = 0;          // step counter, consumed phases

    // One 2-layer LSTM step. xloc: local SMEM input row. rec>=0: record h2
    // into buf row rec (all CTAs). fresh: input row was recorded last phase.
    auto step = [&](const float *xloc, int rec, bool fresh) {
        const int rp = s & 1, wp = rp ^ 1;
        if (fresh) { while (bdone < s) { waitp(mbB, bdone & 1); bdone++; } }

        // ---- layer 1 (no wait needed: inputs local, h1(s-1) ensured) ----
        const float *src = (p < 2) ? xloc + p * 64
                                   : &sm[OFF_HB + rp * 128 + (p - 2) * 64];
        float acc = dot64(w0, src);
        acc += __shfl_xor_sync(0xffffffffu, acc, 1);
        acc += __shfl_xor_sync(0xffffffffu, acc, 2);
        if (p == 0) sm[OFF_GT + rr] = acc + bia0;
        __syncthreads();
        if (tid < 16) {
            float gi = sm[OFF_GT + tid],      gf = sm[OFF_GT + 16 + tid];
            float gg = sm[OFF_GT + 32 + tid], go = sm[OFF_GT + 48 + tid];
            c0 = sigf(gf) * c0 + sigf(gi) * tanhf(gg);
            sm[OFF_HS + tid] = sigf(go) * tanhf(c0);
        }
        __syncthreads();
        if (tid < 8) {
            const float4 *hs = (const float4 *)&sm[OFF_HS];
            float4 a0 = hs[0], a1 = hs[1], a2 = hs[2], a3 = hs[3];
            uint32_t d = wp ? h1d1 : h1d0;
            stc4(d, a0); stc4(d + 16, a1); stc4(d + 32, a2); stc4(d + 48, a3);
            arrive_rel(mbA_r);
        }

        // ---- layer 2: old-h2 partial first, then wait for fresh h1 ----
        while (bdone < s) { waitp(mbB, bdone & 1); bdone++; }     // fast path
        float acc2 = 0.f;
        if (p >= 2)
            acc2 = dot64(w1, &sm[OFF_HB + (2 + rp) * 128 + (p - 2) * 64]);
        while (adone <= s) { waitp(mbA, adone & 1); adone++; }    // real wait
        if (p < 2)
            acc2 = dot64(w1, &sm[OFF_HB + wp * 128 + p * 64]);
        acc2 += __shfl_xor_sync(0xffffffffu, acc2, 1);
        acc2 += __shfl_xor_sync(0xffffffffu, acc2, 2);
        if (p == 0) sm[OFF_GT + rr] = acc2 + bia1;
        __syncthreads();
        if (tid < 16) {
            float gi = sm[OFF_GT + tid],      gf = sm[OFF_GT + 16 + tid];
            float gg = sm[OFF_GT + 32 + tid], go = sm[OFF_GT + 48 + tid];
            c1 = sigf(gf) * c1 + sigf(gi) * tanhf(gg);
            sm[OFF_HS + tid] = sigf(go) * tanhf(c1);
        }
        __syncthreads();
        if (tid < 8) {
            const float4 *hs = (const float4 *)&sm[OFF_HS];
            float4 a0 = hs[0], a1 = hs[1], a2 = hs[2], a3 = hs[3];
            uint32_t d = wp ? h2d1 : h2d0;
            stc4(d, a0); stc4(d + 16, a1); stc4(d + 32, a2); stc4(d + 48, a3);
            if (rec >= 0) {
                uint32_t bd = bufr + (uint32_t)(rec * H + cl * 16) * 4;
                stc4(bd, a0); stc4(bd + 16, a1); stc4(bd + 32, a2); stc4(bd + 48, a3);
            }
            arrive_rel(mbB_r);
        }
        s++;
    };

    // ---------------- encoder ----------------
    for (int t = 0; t < TENC; t++)
        step(&sm[OFF_BUF + t * H], (t == TENC - 1) ? 0 : -1, false);

    // ---------------- decoder ----------------
    for (int k = 0; k < FLEN; k++) {
        for (int t = 0; t <= k; t++)
            step(&sm[OFF_BUF + t * H], t, t == 0);

        // forecast FC (computed redundantly per CTA; rank 0 writes OUT)
        while (bdone < s) { waitp(mbB, bdone & 1); bdone++; }
        const int hp = s & 1;
        const int row = tid >> 1, p2 = tid & 1;
        const float *hv = &sm[OFF_HB + (2 + hp) * 128 + p2 * 64];
        const float *wr = &sm[OFF_WFC + row * 129 + p2 * 64];
        float a = 0.f;
#pragma unroll
        for (int j = 0; j < 64; j++) a = fmaf(wr[j], hv[j], a);
        a += __shfl_xor_sync(0xffffffffu, a, 1);
        if (p2 == 0) {
            float val = a + sm[OFF_BFC + row];
            sm[OFF_BUF + (k + 1) * H + row] = val;
            if (cl == 0) OUT[(grp * FLEN + k) * H + row] = val;
        }
        __syncthreads();
    }

    asm volatile("barrier.cluster.arrive.aligned;" ::: "memory");
    asm volatile("barrier.cluster.wait.aligned;"   ::: "memory");
}

extern "C" void kernel_launch(void *const *d_in, const int *in_sizes, int n_in,
                              void *d_out, int out_size)
{
    const float *X   = (const float *)d_in[0];
    const float *Wih = (const float *)d_in[1];
    const float *Whh = (const float *)d_in[2];
    const float *bih = (const float *)d_in[3];
    const float *bhh = (const float *)d_in[4];
    const float *Wfc = (const float *)d_in[5];
    const float *bfc = (const float *)d_in[6];
    float *OUT = (float *)d_out;

    cudaFuncSetAttribute(wfm_kernel,
                         cudaFuncAttributeMaxDynamicSharedMemorySize,
                         SMEM_BYTES);

    cudaLaunchConfig_t cfg = {};
    cfg.gridDim  = {64, 1, 1};
    cfg.blockDim = {NTH, 1, 1};
    cfg.dynamicSmemBytes = SMEM_BYTES;
    cudaLaunchAttribute attrs[1];
    attrs[0].id = cudaLaunchAttributeClusterDimension;
    attrs[0].val.clusterDim = {8, 1, 1};
    cfg.attrs = attrs;
    cfg.numAttrs = 1;

    cudaLaunchKernelEx(&cfg, wfm_kernel, X, Wih, Whh, bih, bhh, Wfc, bfc, OUT);
}

// round 4
// speedup vs baseline: 2.4577x; 1.3385x over previous
#include <cuda_runtime.h>
#include <cstdint>

// ---------------------------------------------------------------------------
// 2-layer LSTM encoder (168) + O(T^2) decoder replay (14196) = 14364 serial
// steps. 8 clusters x 8 CTAs. Thread map: unit u=tid>>4, gate g=(tid>>2)&3,
// split-K p=tid&3 -> one unit's 4 gates live in ONE warp. Combine is done
// redundantly in registers via shfl butterflies (no SMEM, no __syncthreads
// in the step). h exchange: per-lane scalar st.shared::cluster + remote
// mbarrier arrive (ring-2 barriers). Dots use packed fma.rn.f32x2 with
// bank-conflict-free chunk rotation. Fast ex2/rcp activations.
// ---------------------------------------------------------------------------

#define H    128
#define CPG  8
#define NTH  256
#define TENC 168
#define FLEN 168

typedef unsigned long long u64;

// SMEM float offsets
#define OFF_BUF 0                        // replay buffer / X: 169*128
#define OFF_WFC (169*128)                // Wfc, stride 129:   128*129
#define OFF_BFC (OFF_WFC + 128*129)     // bfc: 128
#define OFF_HB  (OFF_BFC + 128)         // h[(l*2+par)*128]: 512
#define OFF_MB  (OFF_HB + 512)          // 4 mbarriers: A0,A1,B0,B1 (8B each)
#define SMEM_FLOATS (OFF_MB + 8)
#define SMEM_BYTES  (SMEM_FLOATS * 4)

static __device__ __forceinline__ float fast_ex2(float x)
{ float r; asm("ex2.approx.f32 %0,%1;" : "=f"(r) : "f"(x)); return r; }
static __device__ __forceinline__ float fast_rcp(float x)
{ float r; asm("rcp.approx.f32 %0,%1;" : "=f"(r) : "f"(x)); return r; }
static __device__ __forceinline__ float sigf(float x)
{ return fast_rcp(1.0f + fast_ex2(-1.44269504f * x)); }
static __device__ __forceinline__ float tanh_fast(float x)
{ return fmaf(2.0f, sigf(2.0f * x), -1.0f); }

static __device__ __forceinline__ uint32_t s2u(const void *p)
{
    uint32_t a;
    asm("{ .reg .u64 t; cvta.to.shared.u64 t, %1; cvt.u32.u64 %0, t; }"
        : "=r"(a) : "l"(p));
    return a;
}
static __device__ __forceinline__ uint32_t mapa32(uint32_t a, uint32_t r)
{
    uint32_t d;
    asm("mapa.shared::cluster.u32 %0, %1, %2;" : "=r"(d) : "r"(a), "r"(r));
    return d;
}
static __device__ __forceinline__ void stc1(uint32_t a, float v)
{
    asm volatile("st.shared::cluster.f32 [%0], %1;" :: "r"(a), "f"(v) : "memory");
}
static __device__ __forceinline__ void arrive_rel(uint32_t a)
{
    asm volatile("mbarrier.arrive.release.cluster.shared::cluster.b64 _, [%0];"
                 :: "r"(a) : "memory");
}
static __device__ __forceinline__ void waitp(uint32_t a, uint32_t ph)
{
    asm volatile("{ .reg .pred P;\n"
                 "WL%=:\n"
                 " mbarrier.try_wait.parity.acquire.cluster.shared::cta.b64 P, [%0], %1;\n"
                 " @!P bra WL%=;\n"
                 "}" :: "r"(a), "r"(ph) : "memory");
}
static __device__ __forceinline__ void mbinit(uint32_t a, uint32_t n)
{
    asm volatile("mbarrier.init.shared.b64 [%0], %1;" :: "r"(a), "r"(n) : "memory");
}

static __device__ __forceinline__ void fma2(u64 &acc, u64 a, u64 b)
{ asm("fma.rn.f32x2 %0, %1, %2, %0;" : "+l"(acc) : "l"(a), "l"(b)); }
static __device__ __forceinline__ float2 up2(u64 a)
{ float2 r; asm("mov.b64 {%0,%1}, %2;" : "=f"(r.x), "=f"(r.y) : "l"(a)); return r; }

// 64-term dot, weights pre-rotated so chunk slot qq maps to column chunk
// (qq+p)&7 (32B chunks; 4 p-lanes land 8 banks apart -> conflict-free).
static __device__ __forceinline__ float dot64p(const u64 *__restrict__ w,
                                               uint32_t base, int p)
{
    u64 a0 = 0, a1 = 0, a2 = 0, a3 = 0;
#pragma unroll
    for (int qq = 0; qq < 8; qq++) {
        uint32_t ad = base + (uint32_t)(((qq + p) & 7) << 5);
        u64 x0, x1, x2, x3;
        asm volatile("ld.shared.v2.u64 {%0,%1},[%2];" : "=l"(x0), "=l"(x1) : "r"(ad));
        asm volatile("ld.shared.v2.u64 {%0,%1},[%2];" : "=l"(x2), "=l"(x3) : "r"(ad + 16));
        fma2(a0, w[4 * qq + 0], x0);
        fma2(a1, w[4 * qq + 1], x1);
        fma2(a2, w[4 * qq + 2], x2);
        fma2(a3, w[4 * qq + 3], x3);
    }
    float2 f0 = up2(a0), f1 = up2(a1), f2 = up2(a2), f3 = up2(a3);
    return ((f0.x + f0.y) + (f1.x + f1.y)) + ((f2.x + f2.y) + (f3.x + f3.y));
}

__global__ void __launch_bounds__(NTH, 1) wfm_kernel(
    const float *__restrict__ X,   const float *__restrict__ Wih,
    const float *__restrict__ Whh, const float *__restrict__ bih,
    const float *__restrict__ bhh, const float *__restrict__ Wfc,
    const float *__restrict__ bfc, float *__restrict__ OUT)
{
    extern __shared__ float sm[];
    const int tid = threadIdx.x;
    const int grp = blockIdx.x >> 3;
    const int cl  = blockIdx.x & 7;
    const int u   = tid >> 4;          // hidden unit within CTA slice (0..15)
    const int g   = (tid >> 2) & 3;    // gate (i,f,g,o)
    const int p   = tid & 3;           // split-K quarter (64 cols)
    const int idx16 = tid & 15;        // g*4+p

    // ---- weights -> packed u64 registers, chunk-rotated by p ----
    u64 w0[32], w1[32];
    {
        const int row = g * H + cl * 16 + u;
        const float *s0 = (p < 2) ? &Wih[row * H + p * 64]
                                  : &Whh[row * H + (p - 2) * 64];
        const float *s1 = (p < 2) ? &Wih[(512 + row) * H + p * 64]
                                  : &Whh[(512 + row) * H + (p - 2) * 64];
#pragma unroll
        for (int qq = 0; qq < 8; qq++) {
            int c = (qq + p) & 7;
            const u64 *p0 = (const u64 *)(s0 + c * 8);
            const u64 *p1 = (const u64 *)(s1 + c * 8);
#pragma unroll
            for (int m = 0; m < 4; m++) {
                w0[4 * qq + m] = __ldg(p0 + m);
                w1[4 * qq + m] = __ldg(p1 + m);
            }
        }
    }
    const int brow = g * H + cl * 16 + u;
    const float bia0 = __ldg(&bih[brow]) + __ldg(&bhh[brow]);
    const float bia1 = __ldg(&bih[512 + brow]) + __ldg(&bhh[512 + brow]);

    // ---- SMEM staging ----
    for (int i = tid; i < TENC * H; i += NTH)
        sm[OFF_BUF + i] = __ldg(&X[grp * TENC * H + i]);
    for (int i = tid; i < H * H; i += NTH) {
        int r = i >> 7, c = i & 127;
        sm[OFF_WFC + r * 129 + c] = __ldg(&Wfc[i]);
    }
    if (tid < H) sm[OFF_BFC + tid] = __ldg(&bfc[tid]);
    for (int i = tid; i < 512; i += NTH) sm[OFF_HB + i] = 0.f;

    const uint32_t sbase = s2u(sm);
    const uint32_t mbL   = sbase + OFF_MB * 4;   // A0,A1,B0,B1 at +0,+8,+16,+24
    const uint32_t HBA   = sbase + OFF_HB * 4;
    if (tid == 0)
        for (int i = 0; i < 4; i++) mbinit(mbL + 8 * i, 128);
    __syncthreads();
    asm volatile("barrier.cluster.arrive.aligned;" ::: "memory");
    asm volatile("barrier.cluster.wait.aligned;"   ::: "memory");

    // ---- per-lane remote addresses (lanes idx16<8 push to rank idx16) ----
    uint32_t a_unit = 0, a_mb = 0, a_buf = 0;
    {
        uint32_t rk = idx16 & 7;
        uint32_t br = mapa32(sbase, rk);
        a_unit = br + (OFF_HB + cl * 16 + u) * 4;
        a_mb   = br + OFF_MB * 4;
        a_buf  = br + (cl * 16 + u) * 4;     // + rec*512
    }
    const bool pushl = idx16 < 8;

    float c0 = 0.f, c1 = 0.f;
    int s = 0, adone = 0, bdone = 0;

    auto waitB1 = [&] {
        waitp(mbL + 16 + (bdone & 1) * 8, (bdone >> 1) & 1);
        bdone++;
    };
    auto waitA1 = [&] {
        waitp(mbL + (adone & 1) * 8, (adone >> 1) & 1);
        adone++;
    };

    auto step = [&](uint32_t xaddr, int rec, int bneed) {
        const int rp = s & 1, wp = rp ^ 1;
        while (bdone < bneed) waitB1();

        // ---- layer 1: [x | h1(s-1)] ----
        uint32_t qb = (p < 2) ? (xaddr + (uint32_t)p * 256)
                              : (HBA + (uint32_t)rp * 512 + (uint32_t)(p - 2) * 256);
        float v = dot64p(w0, qb, p);
        v += __shfl_xor_sync(0xffffffffu, v, 1);
        v += __shfl_xor_sync(0xffffffffu, v, 2);
        v += bia0;
        float x1 = __shfl_xor_sync(0xffffffffu, v, 4);
        float x2 = __shfl_xor_sync(0xffffffffu, v, 8);
        float x3 = __shfl_xor_sync(0xffffffffu, x1, 8);
        const int g0 = g & 1, g1 = g >> 1;
        float gi = g1 ? (g0 ? x3 : x2) : (g0 ? x1 : v);
        float gf = g1 ? (g0 ? x2 : x3) : (g0 ? v : x1);
        float gg = g1 ? (g0 ? x1 : v) : (g0 ? x3 : x2);
        float go = g1 ? (g0 ? v : x1) : (g0 ? x2 : x3);
        c0 = sigf(gf) * c0 + sigf(gi) * tanh_fast(gg);
        float h1n = sigf(go) * tanh_fast(c0);
        if (pushl) {
            stc1(a_unit + (uint32_t)wp * 512, h1n);
            arrive_rel(a_mb + (uint32_t)(s & 1) * 8);
        }

        // ---- layer 2: [h1(s) | h2(s-1)] ----
        while (bdone < s) waitB1();                      // h2(s-1) ready
        float v2 = 0.f;
        if (p >= 2)
            v2 = dot64p(w1, HBA + (uint32_t)(2 + rp) * 512 + (uint32_t)(p - 2) * 256, p);
        while (adone <= s) waitA1();                     // fresh h1(s)
        if (p < 2)
            v2 = dot64p(w1, HBA + (uint32_t)wp * 512 + (uint32_t)p * 256, p);
        v2 += __shfl_xor_sync(0xffffffffu, v2, 1);
        v2 += __shfl_xor_sync(0xffffffffu, v2, 2);
        v2 += bia1;
        float y1 = __shfl_xor_sync(0xffffffffu, v2, 4);
        float y2 = __shfl_xor_sync(0xffffffffu, v2, 8);
        float y3 = __shfl_xor_sync(0xffffffffu, y1, 8);
        float hi2 = g1 ? (g0 ? y3 : y2) : (g0 ? y1 : v2);
        float hf2 = g1 ? (g0 ? y2 : y3) : (g0 ? v2 : y1);
        float hg2 = g1 ? (g0 ? y1 : v2) : (g0 ? y3 : y2);
        float ho2 = g1 ? (g0 ? v2 : y1) : (g0 ? y2 : y3);
        c1 = sigf(hf2) * c1 + sigf(hi2) * tanh_fast(hg2);
        float h2n = sigf(ho2) * tanh_fast(c1);
        if (pushl) {
            stc1(a_unit + (uint32_t)(2 + wp) * 512, h2n);
            if (rec >= 0) stc1(a_buf + (uint32_t)rec * 512, h2n);
            arrive_rel(a_mb + 16 + (uint32_t)(s & 1) * 8);
        }
        s++;
    };

    // ---------------- encoder ----------------
    for (int t = 0; t < TENC; t++)
        step(sbase + (uint32_t)t * 512, (t == TENC - 1) ? 0 : -1, 0);

    // ---------------- decoder ----------------
    for (int k = 0; k < FLEN; k++) {
        for (int t = 0; t <= k; t++) {
            int bneed = (t < k) ? (s - k + 1) : (k == 0 ? s : 0);
            step(sbase + (uint32_t)t * 512, t, bneed);
        }
        // forecast FC: redundant per CTA; rank 0 writes OUT
        while (bdone < s) waitB1();
        const int hp = s & 1;
        const int row = tid >> 1, p2 = tid & 1;
        const float *hv = &sm[OFF_HB + (2 + hp) * 128 + p2 * 64];
        const float *wr = &sm[OFF_WFC + row * 129 + p2 * 64];
        float a = 0.f;
#pragma unroll
        for (int j = 0; j < 64; j++) a = fmaf(wr[j], hv[j], a);
        a += __shfl_xor_sync(0xffffffffu, a, 1);
        if (p2 == 0) {
            float val = a + sm[OFF_BFC + row];
            sm[OFF_BUF + (k + 1) * H + row] = val;
            if (cl == 0) OUT[(grp * FLEN + k) * H + row] = val;
        }
        __syncthreads();
    }

    asm volatile("barrier.cluster.arrive.aligned;" ::: "memory");
    asm volatile("barrier.cluster.wait.aligned;"   ::: "memory");
}

extern "C" void kernel_launch(void *const *d_in, const int *in_sizes, int n_in,
                              void *d_out, int out_size)
{
    const float *X   = (const float *)d_in[0];
    const float *Wih = (const float *)d_in[1];
    const float *Whh = (const float *)d_in[2];
    const float *bih = (const float *)d_in[3];
    const float *bhh = (const float *)d_in[4];
    const float *Wfc = (const float *)d_in[5];
    const float *bfc = (const float *)d_in[6];
    float *OUT = (float *)d_out;

    cudaFuncSetAttribute(wfm_kernel,
                         cudaFuncAttributeMaxDynamicSharedMemorySize,
                         SMEM_BYTES);

    cudaLaunchConfig_t cfg = {};
    cfg.gridDim  = {64, 1, 1};
    cfg.blockDim = {NTH, 1, 1};
    cfg.dynamicSmemBytes = SMEM_BYTES;
    cudaLaunchAttribute attrs[1];
    attrs[0].id = cudaLaunchAttributeClusterDimension;
    attrs[0].val.clusterDim = {8, 1, 1};
    cfg.attrs = attrs;
    cfg.numAttrs = 1;

    cudaLaunchKernelEx(&cfg, wfm_kernel, X, Wih, Whh, bih, bhh, Wfc, bfc, OUT);
}

// round 6
// speedup vs baseline: 3.1446x; 1.2795x over previous
#include <cuda_runtime.h>
#include <cstdint>

// ---------------------------------------------------------------------------
// 2-layer LSTM encoder (168) + O(T^2) decoder replay (14196) = 14364 serial
// steps. 8 clusters x 8 CTAs (one cluster per batch element; CTA owns 16
// hidden units = 64 gate rows/layer, weights in registers).
// Decomposition: warp w = (row-half w>>2, split-quarter p=w&3); all 32
// lanes of a warp read the SAME input chunk -> every LDS is a broadcast
// (1 crossbar phase). Cross-p reduce via part[row][p] in SMEM + bar. Warp 0
// does gate-combine (MUFU confined to 1 warp) and pushes h: lane r serves
// rank r with 4x st.shared::cluster.v4 + ONE release-arrive (8 arrives per
// mbarrier phase instead of 128). Ring-2 mbarriers per direction.
// ---------------------------------------------------------------------------

#define H    128
#define CPG  8
#define NTH  256
#define TENC 168
#define FLEN 168

typedef unsigned long long u64;

// SMEM float offsets
#define OFF_BUF 0                         // replay buffer / X: 169*128
#define OFF_WFC (169*128)                 // Wfc, stride 129:   128*129
#define OFF_BFC (OFF_WFC + 128*129)       // bfc: 128
#define OFF_HB  (OFF_BFC + 128)           // h[(l*2+par)*128]: 512
#define OFF_P1  (OFF_HB + 512)            // layer-1 partials [row64][p4]: 256
#define OFF_P2  (OFF_P1 + 256)            // layer-2 partials: 256
#define OFF_HS  (OFF_P2 + 256)            // h stage: 16
#define OFF_MB  (OFF_HS + 16)             // mbarriers A0,A1,B0,B1 (8B each)
#define SMEM_FLOATS (OFF_MB + 8)
#define SMEM_BYTES  (SMEM_FLOATS * 4)     // ~157 KB

static __device__ __forceinline__ float fast_ex2(float x)
{ float r; asm("ex2.approx.f32 %0,%1;" : "=f"(r) : "f"(x)); return r; }
static __device__ __forceinline__ float fast_rcp(float x)
{ float r; asm("rcp.approx.f32 %0,%1;" : "=f"(r) : "f"(x)); return r; }
static __device__ __forceinline__ float sigf(float x)
{ return fast_rcp(1.0f + fast_ex2(-1.44269504f * x)); }
static __device__ __forceinline__ float tanh_fast(float x)
{ return fmaf(2.0f, sigf(2.0f * x), -1.0f); }

static __device__ __forceinline__ uint32_t s2u(const void *p)
{
    uint32_t a;
    asm("{ .reg .u64 t; cvta.to.shared.u64 t, %1; cvt.u32.u64 %0, t; }"
        : "=r"(a) : "l"(p));
    return a;
}
static __device__ __forceinline__ uint32_t mapa32(uint32_t a, uint32_t r)
{
    uint32_t d;
    asm("mapa.shared::cluster.u32 %0, %1, %2;" : "=r"(d) : "r"(a), "r"(r));
    return d;
}
static __device__ __forceinline__ void stc4(uint32_t a, float4 v)
{
    asm volatile("st.shared::cluster.v4.f32 [%0], {%1,%2,%3,%4};"
                 :: "r"(a), "f"(v.x), "f"(v.y), "f"(v.z), "f"(v.w) : "memory");
}
static __device__ __forceinline__ void arrive_rel(uint32_t a)
{
    asm volatile("mbarrier.arrive.release.cluster.shared::cluster.b64 _, [%0];"
                 :: "r"(a) : "memory");
}
static __device__ __forceinline__ void waitp(uint32_t a, uint32_t ph)
{
    asm volatile("{ .reg .pred P;\n"
                 "WL%=:\n"
                 " mbarrier.try_wait.parity.acquire.cluster.shared::cta.b64 P, [%0], %1;\n"
                 " @!P bra WL%=;\n"
                 "}" :: "r"(a), "r"(ph) : "memory");
}
static __device__ __forceinline__ void mbinit(uint32_t a, uint32_t n)
{
    asm volatile("mbarrier.init.shared.b64 [%0], %1;" :: "r"(a), "r"(n) : "memory");
}

static __device__ __forceinline__ void fma2(u64 &acc, u64 a, u64 b)
{ asm("fma.rn.f32x2 %0, %1, %2, %0;" : "+l"(acc) : "l"(a), "l"(b)); }
static __device__ __forceinline__ float2 up2(u64 a)
{ float2 r; asm("mov.b64 {%0,%1}, %2;" : "=f"(r.x), "=f"(r.y) : "l"(a)); return r; }

// 64-term dot; all lanes of the warp read the SAME addresses (broadcast).
static __device__ __forceinline__ float dot64b(const u64 *__restrict__ w,
                                               uint32_t base)
{
    u64 a0 = 0, a1 = 0, a2 = 0, a3 = 0;
#pragma unroll
    for (int q = 0; q < 8; q++) {
        uint32_t ad = base + (uint32_t)(q << 5);
        u64 x0, x1, x2, x3;
        asm volatile("ld.shared.v2.u64 {%0,%1},[%2];" : "=l"(x0), "=l"(x1) : "r"(ad));
        asm volatile("ld.shared.v2.u64 {%0,%1},[%2];" : "=l"(x2), "=l"(x3) : "r"(ad + 16));
        fma2(a0, w[4 * q + 0], x0);
        fma2(a1, w[4 * q + 1], x1);
        fma2(a2, w[4 * q + 2], x2);
        fma2(a3, w[4 * q + 3], x3);
    }
    float2 f0 = up2(a0), f1 = up2(a1), f2 = up2(a2), f3 = up2(a3);
    return ((f0.x + f0.y) + (f1.x + f1.y)) + ((f2.x + f2.y) + (f3.x + f3.y));
}

__global__ void __launch_bounds__(NTH, 1) wfm_kernel(
    const float *__restrict__ X,   const float *__restrict__ Wih,
    const float *__restrict__ Whh, const float *__restrict__ bih,
    const float *__restrict__ bhh, const float *__restrict__ Wfc,
    const float *__restrict__ bfc, float *__restrict__ OUT)
{
    extern __shared__ float sm[];
    const int tid  = threadIdx.x;
    const int grp  = blockIdx.x >> 3;
    const int cl   = blockIdx.x & 7;
    const int wrp  = tid >> 5;
    const int lane = tid & 31;
    const int p    = wrp & 3;                  // split-quarter (64 cols)
    const int r    = ((wrp >> 2) << 5) + lane; // gate row 0..63 (= g*16+u)

    // ---- weights -> registers: row r, quarter p, both layers ----
    u64 w0[32], w1[32];
    {
        const int g = r >> 4, u = r & 15;
        const int R = g * H + cl * 16 + u;     // global gate row (layer stride 512)
        const float *s0 = (p < 2) ? &Wih[R * H + p * 64]
                                  : &Whh[R * H + (p - 2) * 64];
        const float *s1 = (p < 2) ? &Wih[(512 + R) * H + p * 64]
                                  : &Whh[(512 + R) * H + (p - 2) * 64];
        const u64 *p0 = (const u64 *)s0, *p1 = (const u64 *)s1;
#pragma unroll
        for (int i = 0; i < 32; i++) { w0[i] = __ldg(p0 + i); w1[i] = __ldg(p1 + i); }
    }
    // ---- per-unit biases (used by warp 0 lanes<16; ul = unit) ----
    const int ul = lane & 15;
    float bi0[4], bi1[4];
#pragma unroll
    for (int g2 = 0; g2 < 4; g2++) {
        int R = g2 * H + cl * 16 + ul;
        bi0[g2] = __ldg(&bih[R]) + __ldg(&bhh[R]);
        bi1[g2] = __ldg(&bih[512 + R]) + __ldg(&bhh[512 + R]);
    }

    // ---- SMEM staging ----
    for (int i = tid; i < TENC * H; i += NTH)
        sm[OFF_BUF + i] = __ldg(&X[grp * TENC * H + i]);
    for (int i = tid; i < H * H; i += NTH) {
        int rr = i >> 7, c = i & 127;
        sm[OFF_WFC + rr * 129 + c] = __ldg(&Wfc[i]);
    }
    if (tid < H) sm[OFF_BFC + tid] = __ldg(&bfc[tid]);
    for (int i = tid; i < 512; i += NTH) sm[OFF_HB + i] = 0.f;

    const uint32_t sbase = s2u(sm);
    const uint32_t mbL   = sbase + OFF_MB * 4;  // A0,A1,B0,B1 @ +0,+8,+16,+24
    const uint32_t HBA   = sbase + OFF_HB * 4;
    const uint32_t P1A   = sbase + OFF_P1 * 4;
    const uint32_t P2A   = sbase + OFF_P2 * 4;
    if (tid == 0)
        for (int i = 0; i < 4; i++) mbinit(mbL + 8 * i, CPG);
    __syncthreads();
    asm volatile("barrier.cluster.arrive.aligned;" ::: "memory");
    asm volatile("barrier.cluster.wait.aligned;"   ::: "memory");

    // ---- push addresses: warp-0 lane rk (<8) serves cluster rank rk ----
    uint32_t a_hb = 0, a_mb = 0, a_buf = 0;
    if (wrp == 0 && lane < 8) {
        uint32_t br = mapa32(sbase, (uint32_t)lane);
        a_hb  = br + OFF_HB * 4 + cl * 64;    // + par*512 (h1) / +(2+par)*512 (h2)
        a_mb  = br + OFF_MB * 4;
        a_buf = br + OFF_BUF * 4 + cl * 64;   // + rec*512
    }

    float c0 = 0.f, c1 = 0.f;                 // c-state (warp0 lanes<16)
    int s = 0, adone = 0, bdone = 0;

    auto waitA = [&] { waitp(mbL + (adone & 1) * 8, (adone >> 1) & 1); adone++; };
    auto waitB = [&] { waitp(mbL + 16 + (bdone & 1) * 8, (bdone >> 1) & 1); bdone++; };

    auto step = [&](uint32_t xaddr, int rec, int bneed) {
        const int rp = s & 1, wp = rp ^ 1;

        // ---- layer 1 ----
        if (p < 2) {                     // x half: BUF row (freshness: bneed)
            while (bdone < bneed) waitB();
        } else {                         // h1(s-1) half
            while (adone < s) waitA();
        }
        uint32_t b1 = (p < 2) ? (xaddr + (uint32_t)p * 256)
                              : (HBA + (uint32_t)rp * 512 + (uint32_t)(p - 2) * 256);
        float v = dot64b(w0, b1);
        { uint32_t sa = P1A + (uint32_t)(r * 4 + p) * 4;
          asm volatile("st.shared.f32 [%0],%1;" :: "r"(sa), "f"(v) : "memory"); }
        __syncthreads();

        if (wrp == 0) {
            if (lane < 16) {
                float4 q0 = *(float4 *)&sm[OFF_P1 + (0 * 16 + lane) * 4];
                float4 q1 = *(float4 *)&sm[OFF_P1 + (1 * 16 + lane) * 4];
                float4 q2 = *(float4 *)&sm[OFF_P1 + (2 * 16 + lane) * 4];
                float4 q3 = *(float4 *)&sm[OFF_P1 + (3 * 16 + lane) * 4];
                float gi = q0.x + q0.y + q0.z + q0.w + bi0[0];
                float gf = q1.x + q1.y + q1.z + q1.w + bi0[1];
                float gg = q2.x + q2.y + q2.z + q2.w + bi0[2];
                float go = q3.x + q3.y + q3.z + q3.w + bi0[3];
                c0 = sigf(gf) * c0 + sigf(gi) * tanh_fast(gg);
                sm[OFF_HS + lane] = sigf(go) * tanh_fast(c0);
            }
            __syncwarp();
            if (lane < 8) {
                float4 h0 = *(float4 *)&sm[OFF_HS + 0];
                float4 h1v = *(float4 *)&sm[OFF_HS + 4];
                float4 h2v = *(float4 *)&sm[OFF_HS + 8];
                float4 h3v = *(float4 *)&sm[OFF_HS + 12];
                uint32_t d = a_hb + (uint32_t)wp * 512;
                stc4(d, h0); stc4(d + 16, h1v); stc4(d + 32, h2v); stc4(d + 48, h3v);
                arrive_rel(a_mb + (uint32_t)(s & 1) * 8);
            }
        }

        // ---- layer 2 ----
        while (bdone < s) waitB();       // h2(s-1) landed
        float v2;
        if (p >= 2) {
            v2 = dot64b(w1, HBA + (uint32_t)(2 + rp) * 512 + (uint32_t)(p - 2) * 256);
        } else {
            while (adone <= s) waitA();  // fresh h1(s)
            v2 = dot64b(w1, HBA + (uint32_t)wp * 512 + (uint32_t)p * 256);
        }
        { uint32_t sa = P2A + (uint32_t)(r * 4 + p) * 4;
          asm volatile("st.shared.f32 [%0],%1;" :: "r"(sa), "f"(v2) : "memory"); }
        __syncthreads();

        if (wrp == 0) {
            if (lane < 16) {
                float4 q0 = *(float4 *)&sm[OFF_P2 + (0 * 16 + lane) * 4];
                float4 q1 = *(float4 *)&sm[OFF_P2 + (1 * 16 + lane) * 4];
                float4 q2 = *(float4 *)&sm[OFF_P2 + (2 * 16 + lane) * 4];
                float4 q3 = *(float4 *)&sm[OFF_P2 + (3 * 16 + lane) * 4];
                float gi = q0.x + q0.y + q0.z + q0.w + bi1[0];
                float gf = q1.x + q1.y + q1.z + q1.w + bi1[1];
                float gg = q2.x + q2.y + q2.z + q2.w + bi1[2];
                float go = q3.x + q3.y + q3.z + q3.w + bi1[3];
                c1 = sigf(gf) * c1 + sigf(gi) * tanh_fast(gg);
                sm[OFF_HS + lane] = sigf(go) * tanh_fast(c1);
            }
            __syncwarp();
            if (lane < 8) {
                float4 h0 = *(float4 *)&sm[OFF_HS + 0];
                float4 h1v = *(float4 *)&sm[OFF_HS + 4];
                float4 h2v = *(float4 *)&sm[OFF_HS + 8];
                float4 h3v = *(float4 *)&sm[OFF_HS + 12];
                uint32_t d = a_hb + (uint32_t)(2 + wp) * 512;
                stc4(d, h0); stc4(d + 16, h1v); stc4(d + 32, h2v); stc4(d + 48, h3v);
                if (rec >= 0) {
                    uint32_t bd = a_buf + (uint32_t)rec * 512;
                    stc4(bd, h0); stc4(bd + 16, h1v);
                    stc4(bd + 32, h2v); stc4(bd + 48, h3v);
                }
                arrive_rel(a_mb + 16 + (uint32_t)(s & 1) * 8);
            }
        }
        s++;
    };

    // ---------------- encoder ----------------
    for (int t = 0; t < TENC; t++)
        step(sbase + (uint32_t)t * 512, (t == TENC - 1) ? 0 : -1, 0);

    // ---------------- decoder ----------------
    for (int k = 0; k < FLEN; k++) {
        for (int t = 0; t <= k; t++) {
            int bneed = (t < k) ? (s - k + 1) : (k == 0 ? s : 0);
            step(sbase + (uint32_t)t * 512, t, bneed);
        }
        // forecast FC (redundant per CTA; rank 0 writes OUT)
        while (bdone < s) waitB();
        const int hp = s & 1;
        const int row = tid >> 1, p2 = tid & 1;
        const float *hv = &sm[OFF_HB + (2 + hp) * 128 + p2 * 64];
        const float *wr = &sm[OFF_WFC + row * 129 + p2 * 64];
        float a = 0.f;
#pragma unroll
        for (int j = 0; j < 64; j++) a = fmaf(wr[j], hv[j], a);
        a += __shfl_xor_sync(0xffffffffu, a, 1);
        if (p2 == 0) {
            float val = a + sm[OFF_BFC + row];
            sm[OFF_BUF + (k + 1) * H + row] = val;
            if (cl == 0) OUT[(grp * FLEN + k) * H + row] = val;
        }
        __syncthreads();
    }

    asm volatile("barrier.cluster.arrive.aligned;" ::: "memory");
    asm volatile("barrier.cluster.wait.aligned;"   ::: "memory");
}

extern "C" void kernel_launch(void *const *d_in, const int *in_sizes, int n_in,
                              void *d_out, int out_size)
{
    const float *X   = (const float *)d_in[0];
    const float *Wih = (const float *)d_in[1];
    const float *Whh = (const float *)d_in[2];
    const float *bih = (const float *)d_in[3];
    const float *bhh = (const float *)d_in[4];
    const float *Wfc = (const float *)d_in[5];
    const float *bfc = (const float *)d_in[6];
    float *OUT = (float *)d_out;

    cudaFuncSetAttribute(wfm_kernel,
                         cudaFuncAttributeMaxDynamicSharedMemorySize,
                         SMEM_BYTES);

    cudaLaunchConfig_t cfg = {};
    cfg.gridDim  = {64, 1, 1};
    cfg.blockDim = {NTH, 1, 1};
    cfg.dynamicSmemBytes = SMEM_BYTES;
    cudaLaunchAttribute attrs[1];
    attrs[0].id = cudaLaunchAttributeClusterDimension;
    attrs[0].val.clusterDim = {8, 1, 1};
    cfg.attrs = attrs;
    cfg.numAttrs = 1;

    cudaLaunchKernelEx(&cfg, wfm_kernel, X, Wih, Whh, bih, bhh, Wfc, bfc, OUT);
}

// round 8
// speedup vs baseline: 4.2691x; 1.3576x over previous
#include <cuda_runtime.h>
#include <cstdint>

// ---------------------------------------------------------------------------
// Layer-pipelined cluster LSTM, seqno-synchronized (no mbarriers).
// 8 clusters (batch) x 8 CTAs: ranks 0-3 run layer 1, ranks 4-7 run layer 2
// (each CTA owns 32 units of its layer; weights in registers, one layer).
// Layer-2 step s overlaps layer-1 step s+1. Exchange: push warps write h via
// st.shared::cluster.v4 then st.release.cluster a monotonic seq (s+1) into a
// per-(CTA,warp) slot on every rank; consumers poll min of 8 ld.acquire.
// Monotonic seq => no parity aliasing, lagging consumers pay one check.
// ---------------------------------------------------------------------------

#define H    128
#define NTH  256
#define TENC 168
#define FLEN 168

typedef unsigned long long u64;

// SMEM float offsets
#define OFF_BUF 0                        // replay buffer / X: 169*128
#define OFF_WFC (169*128)                // Wfc, stride 129: 128*129
#define OFF_BFC (OFF_WFC + 128*129)      // bfc: 128
#define OFF_HB  (OFF_BFC + 128)          // [h1_0,h1_1,h2_0,h2_1][128]: 512
#define OFF_P   (OFF_HB + 512)           // partials, double-buffered: 2*256
#define OFF_HS  (OFF_P + 512)            // h stage: 32
#define OFF_SQ  (OFF_HS + 32)            // aseq[8], bseq[8] (u32 each)
#define SMEM_FLOATS (OFF_SQ + 16)
#define SMEM_BYTES  (SMEM_FLOATS * 4)

static __device__ __forceinline__ float fast_ex2(float x)
{ float r; asm("ex2.approx.f32 %0,%1;" : "=f"(r) : "f"(x)); return r; }
static __device__ __forceinline__ float fast_rcp(float x)
{ float r; asm("rcp.approx.f32 %0,%1;" : "=f"(r) : "f"(x)); return r; }
static __device__ __forceinline__ float sigf(float x)
{ return fast_rcp(1.0f + fast_ex2(-1.44269504f * x)); }
static __device__ __forceinline__ float tanh_fast(float x)
{ return fmaf(2.0f, sigf(2.0f * x), -1.0f); }

static __device__ __forceinline__ uint32_t s2u(const void *p)
{
    uint32_t a;
    asm("{ .reg .u64 t; cvta.to.shared.u64 t, %1; cvt.u32.u64 %0, t; }"
        : "=r"(a) : "l"(p));
    return a;
}
static __device__ __forceinline__ uint32_t mapa32(uint32_t a, uint32_t r)
{
    uint32_t d;
    asm("mapa.shared::cluster.u32 %0, %1, %2;" : "=r"(d) : "r"(a), "r"(r));
    return d;
}
static __device__ __forceinline__ void stc4(uint32_t a, float4 v)
{
    asm volatile("st.shared::cluster.v4.f32 [%0], {%1,%2,%3,%4};"
                 :: "r"(a), "f"(v.x), "f"(v.y), "f"(v.z), "f"(v.w) : "memory");
}
static __device__ __forceinline__ void strel(uint32_t a, uint32_t v)
{
    asm volatile("st.release.cluster.shared::cluster.u32 [%0], %1;"
                 :: "r"(a), "r"(v) : "memory");
}
static __device__ __forceinline__ uint32_t ldacq(uint32_t a)
{
    uint32_t v;
    asm volatile("ld.acquire.cluster.shared::cta.u32 %0, [%1];"
                 : "=r"(v) : "r"(a) : "memory");
    return v;
}
// Wait until all 8 producer slots at base reach >= n. Monotonic, alias-free.
static __device__ __forceinline__ void wait8(uint32_t base, int n)
{
    if (n <= 0) return;
    const uint32_t un = (uint32_t)n;
    for (;;) {
        uint32_t v0 = ldacq(base +  0), v1 = ldacq(base +  4);
        uint32_t v2 = ldacq(base +  8), v3 = ldacq(base + 12);
        uint32_t v4 = ldacq(base + 16), v5 = ldacq(base + 20);
        uint32_t v6 = ldacq(base + 24), v7 = ldacq(base + 28);
        uint32_t m = min(min(min(v0, v1), min(v2, v3)),
                         min(min(v4, v5), min(v6, v7)));
        if (m >= un) break;
    }
}

static __device__ __forceinline__ void fma2(u64 &acc, u64 a, u64 b)
{ asm("fma.rn.f32x2 %0, %1, %2, %0;" : "+l"(acc) : "l"(a), "l"(b)); }
static __device__ __forceinline__ float2 up2(u64 a)
{ float2 r; asm("mov.b64 {%0,%1}, %2;" : "=f"(r.x), "=f"(r.y) : "l"(a)); return r; }

// 128-term dot; all lanes read the SAME addresses (pure broadcast).
static __device__ __forceinline__ float dot128b(const u64 *__restrict__ w,
                                                uint32_t base)
{
    u64 a0 = 0, a1 = 0, a2 = 0, a3 = 0;
#pragma unroll
    for (int q = 0; q < 16; q++) {
        uint32_t ad = base + (uint32_t)(q << 5);
        u64 x0, x1, x2, x3;
        asm volatile("ld.shared.v2.u64 {%0,%1},[%2];" : "=l"(x0), "=l"(x1) : "r"(ad));
        asm volatile("ld.shared.v2.u64 {%0,%1},[%2];" : "=l"(x2), "=l"(x3) : "r"(ad + 16));
        fma2(a0, w[4 * q + 0], x0);
        fma2(a1, w[4 * q + 1], x1);
        fma2(a2, w[4 * q + 2], x2);
        fma2(a3, w[4 * q + 3], x3);
    }
    float2 f0 = up2(a0), f1 = up2(a1), f2 = up2(a2), f3 = up2(a3);
    return ((f0.x + f0.y) + (f1.x + f1.y)) + ((f2.x + f2.y) + (f3.x + f3.y));
}

__global__ void __launch_bounds__(NTH, 1) wfm_kernel(
    const float *__restrict__ X,   const float *__restrict__ Wih,
    const float *__restrict__ Whh, const float *__restrict__ bih,
    const float *__restrict__ bhh, const float *__restrict__ Wfc,
    const float *__restrict__ bfc, float *__restrict__ OUT)
{
    extern __shared__ float sm[];
    const int tid  = threadIdx.x;
    const int grp  = blockIdx.x >> 3;
    const int cl   = blockIdx.x & 7;
    const int wrp  = tid >> 5;
    const int lane = tid & 31;
    const int role = cl >> 2;              // 0: layer-1 CTA, 1: layer-2 CTA
    const int base = (cl & 3) * 32;        // owned unit base within H
    const int p    = wrp & 1;              // 0: x/Wih half, 1: h/Whh half
    const int rloc = ((wrp >> 1) << 5) + lane;  // local gate row 0..127

    // ---- weights -> registers: local row rloc, half p, own layer ----
    u64 w[64];
    {
        const int g = rloc >> 5, uu = rloc & 31;
        const int R = role * 512 + g * H + base + uu;
        const float *src = (p == 0) ? &Wih[R * H] : &Whh[R * H];
        const u64 *ps = (const u64 *)src;
#pragma unroll
        for (int i = 0; i < 64; i++) w[i] = __ldg(ps + i);
    }
    // ---- combine biases (warps 0,1; unit cu = wrp*16 + lane%16) ----
    const int cu = ((wrp & 1) << 4) + (lane & 15);
    float bi[4];
#pragma unroll
    for (int g2 = 0; g2 < 4; g2++) {
        int R = role * 512 + g2 * H + base + cu;
        bi[g2] = __ldg(&bih[R]) + __ldg(&bhh[R]);
    }

    // ---- SMEM staging ----
    for (int i = tid; i < TENC * H; i += NTH)
        sm[OFF_BUF + i] = __ldg(&X[grp * TENC * H + i]);
    for (int i = tid; i < H * H; i += NTH) {
        int rr = i >> 7, c = i & 127;
        sm[OFF_WFC + rr * 129 + c] = __ldg(&Wfc[i]);
    }
    if (tid < H) sm[OFF_BFC + tid] = __ldg(&bfc[tid]);
    for (int i = tid; i < 512 + 512 + 32 + 16; i += NTH)
        sm[OFF_HB + i] = 0.f;                     // HB, partials, HS, seq = 0

    const uint32_t sbase = s2u(sm);
    const uint32_t HBA   = sbase + OFF_HB * 4;
    const uint32_t SQA   = sbase + OFF_SQ * 4;    // aseq[8]
    const uint32_t SQB   = SQA + 32;              // bseq[8]
    __syncthreads();
    asm volatile("barrier.cluster.arrive.aligned;" ::: "memory");
    asm volatile("barrier.cluster.wait.aligned;"   ::: "memory");

    // ---- push addresses (warps 0,1; lane<8 -> destination rank = lane) ----
    uint32_t a_hb = 0, a_sq = 0, a_buf = 0;
    if (wrp < 2 && lane < 8) {
        uint32_t br = mapa32(sbase, (uint32_t)lane);
        a_hb  = br + OFF_HB * 4 + (uint32_t)(base + (wrp << 4)) * 4;
        a_sq  = br + OFF_SQ * 4 + (uint32_t)(role * 8 + (cl & 3) * 2 + wrp) * 4;
        a_buf = br + OFF_BUF * 4 + (uint32_t)(base + (wrp << 4)) * 4;
    }

    float cc = 0.f;                     // c-state for unit cu (warps 0,1 lanes<16)
    int s = 0;

    // combine + push. hbslot: HB slot index for this layer's h(s). rec: replay
    // row to record (role 1 decode/enc-last only, ranks 0-3).
    auto combine_push = [&](int hbslot, int rec) {
        const float *pp = &sm[OFF_P + (s & 1) * 256];
        if (lane < 16) {
            float2 q0 = *(const float2 *)&pp[0 * 64 + cu * 2];
            float2 q1 = *(const float2 *)&pp[1 * 64 + cu * 2];
            float2 q2 = *(const float2 *)&pp[2 * 64 + cu * 2];
            float2 q3 = *(const float2 *)&pp[3 * 64 + cu * 2];
            float gi = q0.x + q0.y + bi[0];
            float gf = q1.x + q1.y + bi[1];
            float gg = q2.x + q2.y + bi[2];
            float go = q3.x + q3.y + bi[3];
            cc = sigf(gf) * cc + sigf(gi) * tanh_fast(gg);
            sm[OFF_HS + cu] = sigf(go) * tanh_fast(cc);
        }
        __syncwarp();
        if (role == 0) wait8(SQB, s - 1);    // WAR gate on h1 ping-pong slot
        if (lane < 8) {
            const float4 *hs = (const float4 *)&sm[OFF_HS + ((wrp & 1) << 4)];
            float4 h0 = hs[0], h1 = hs[1], h2 = hs[2], h3 = hs[3];
            uint32_t d = a_hb + (uint32_t)hbslot * 512;
            stc4(d, h0); stc4(d + 16, h1); stc4(d + 32, h2); stc4(d + 48, h3);
            if (rec >= 0 && lane < 4) {
                uint32_t bd = a_buf + (uint32_t)rec * 512;
                stc4(bd, h0); stc4(bd + 16, h1); stc4(bd + 32, h2); stc4(bd + 48, h3);
            }
            strel(a_sq, (uint32_t)(s + 1));
        }
    };

    auto stepL1 = [&](uint32_t xaddr, int bneed) {
        if (p == 0) wait8(SQB, bneed);        // replay-row freshness
        else        wait8(SQA, s);            // h1(s-1) ready
        uint32_t ib = (p == 0) ? xaddr : (HBA + (uint32_t)(s & 1) * 512);
        float v = dot128b(w, ib);
        uint32_t sa = sbase + (uint32_t)(OFF_P + (s & 1) * 256 + rloc * 2 + p) * 4;
        asm volatile("st.shared.f32 [%0],%1;" :: "r"(sa), "f"(v) : "memory");
        __syncthreads();
        if (wrp < 2) combine_push((s + 1) & 1, -1);
        s++;
    };

    auto stepL2 = [&](int rec) {
        if (p == 0) wait8(SQA, s + 1);        // fresh h1(s)
        else        wait8(SQB, s);            // h2(s-1) ready
        uint32_t ib = (p == 0) ? (HBA + (uint32_t)((s + 1) & 1) * 512)
                               : (HBA + (uint32_t)(2 + (s & 1)) * 512);
        float v = dot128b(w, ib);
        uint32_t sa = sbase + (uint32_t)(OFF_P + (s & 1) * 256 + rloc * 2 + p) * 4;
        asm volatile("st.shared.f32 [%0],%1;" :: "r"(sa), "f"(v) : "memory");
        __syncthreads();
        if (wrp < 2) combine_push(2 + ((s + 1) & 1), rec);
        s++;
    };

    if (role == 0) {
        // ---------------- layer-1 pipeline stage ----------------
        for (int t = 0; t < TENC; t++) stepL1(sbase + (uint32_t)t * 512, 0);
        for (int k = 0; k < FLEN; k++) {
            for (int t = 0; t <= k; t++)
                stepL1(sbase + (uint32_t)t * 512,
                       (t < k) ? (s - k + 1) : (k == 0 ? s : 0));
            // forecast FC (redundant across ranks 0-3; rank 0 writes OUT)
            wait8(SQB, s);                    // h2 of last step landed
            const int hp = s & 1;
            const int row = tid >> 1, p2 = tid & 1;
            const float *hv = &sm[OFF_HB + (2 + hp) * 128 + p2 * 64];
            const float *wr = &sm[OFF_WFC + row * 129 + p2 * 64];
            float a = 0.f;
#pragma unroll
            for (int j = 0; j < 64; j++) a = fmaf(wr[j], hv[j], a);
            a += __shfl_xor_sync(0xffffffffu, a, 1);
            if (p2 == 0) {
                float val = a + sm[OFF_BFC + row];
                sm[OFF_BUF + (k + 1) * H + row] = val;
                if (cl == 0) OUT[(grp * FLEN + k) * H + row] = val;
            }
            __syncthreads();
        }
    } else {
        // ---------------- layer-2 pipeline stage ----------------
        for (int t = 0; t < TENC; t++) stepL2((t == TENC - 1) ? 0 : -1);
        for (int k = 0; k < FLEN; k++)
            for (int t = 0; t <= k; t++) stepL2(t);
    }

    asm volatile("barrier.cluster.arrive.aligned;" ::: "memory");
    asm volatile("barrier.cluster.wait.aligned;"   ::: "memory");
}

extern "C" void kernel_launch(void *const *d_in, const int *in_sizes, int n_in,
                              void *d_out, int out_size)
{
    const float *X   = (const float *)d_in[0];
    const float *Wih = (const float *)d_in[1];
    const float *Whh = (const float *)d_in[2];
    const float *bih = (const float *)d_in[3];
    const float *bhh = (const float *)d_in[4];
    const float *Wfc = (const float *)d_in[5];
    const float *bfc = (const float *)d_in[6];
    float *OUT = (float *)d_out;

    cudaFuncSetAttribute(wfm_kernel,
                         cudaFuncAttributeMaxDynamicSharedMemorySize,
                         SMEM_BYTES);

    cudaLaunchConfig_t cfg = {};
    cfg.gridDim  = {64, 1, 1};
    cfg.blockDim = {NTH, 1, 1};
    cfg.dynamicSmemBytes = SMEM_BYTES;
    cudaLaunchAttribute attrs[1];
    attrs[0].id = cudaLaunchAttributeClusterDimension;
    attrs[0].val.clusterDim = {8, 1, 1};
    cfg.attrs = attrs;
    cfg.numAttrs = 1;

    cudaLaunchKernelEx(&cfg, wfm_kernel, X, Wih, Whh, bih, bhh, Wfc, bfc, OUT);
}